// round 1
// baseline (speedup 1.0000x reference)
#include <cuda_runtime.h>

// Problem constants
// B=4, S=2048, D=512, H=8, HD=64

__device__ float g_Q[4 * 8 * 2048 * 64];   // [B,H,S,HD]
__device__ float g_K[4 * 8 * 2048 * 64];
__device__ float g_V[4 * 8 * 2048 * 64];
__device__ float g_O[4 * 2048 * 512];      // [B,S,D] attention output

// ---------------------------------------------------------------------------
// Fused QKV projection GEMM: C = A(8192x512) @ W(512x512) + bias,
// stored in head layout [B,H,S,HD]. blockIdx.z selects Q/K/V.
// 128x128 tile, BK=16, 256 threads, 8x8 micro-tile.
// ---------------------------------------------------------------------------
__global__ __launch_bounds__(256) void qkv_proj_kernel(
    const float* __restrict__ Qin, const float* __restrict__ Kin,
    const float* __restrict__ Vin,
    const float* __restrict__ Wq, const float* __restrict__ bq,
    const float* __restrict__ Wk, const float* __restrict__ bk,
    const float* __restrict__ Wv, const float* __restrict__ bv)
{
    const int mat = blockIdx.z;
    const float* A    = (mat == 0) ? Qin : (mat == 1) ? Kin : Vin;
    const float* W    = (mat == 0) ? Wq  : (mat == 1) ? Wk  : Wv;
    const float* bias = (mat == 0) ? bq  : (mat == 1) ? bk  : bv;
    float* dst        = (mat == 0) ? g_Q : (mat == 1) ? g_K : g_V;

    __shared__ float As[16][132];   // [k][m], padded
    __shared__ float Bs[16][132];   // [k][n], padded

    const int tid = threadIdx.x;
    const int tx = tid & 15, ty = tid >> 4;
    const int row0 = blockIdx.y * 128;
    const int col0 = blockIdx.x * 128;

    float acc[8][8];
#pragma unroll
    for (int i = 0; i < 8; i++)
#pragma unroll
        for (int j = 0; j < 8; j++) acc[i][j] = 0.f;

    const int ar = tid >> 2;          // 0..63 (A tile row, two iters)
    const int ak = (tid & 3) * 4;     // k offset
    const int br = tid >> 5;          // 0..7  (B tile k row, two iters)
    const int bc = (tid & 31) * 4;    // col offset

    for (int k0 = 0; k0 < 512; k0 += 16) {
#pragma unroll
        for (int i = 0; i < 2; i++) {
            float4 a4 = *(const float4*)&A[(size_t)(row0 + ar + i * 64) * 512 + k0 + ak];
            As[ak + 0][ar + i * 64] = a4.x;
            As[ak + 1][ar + i * 64] = a4.y;
            As[ak + 2][ar + i * 64] = a4.z;
            As[ak + 3][ar + i * 64] = a4.w;
        }
#pragma unroll
        for (int i = 0; i < 2; i++) {
            float4 b4 = *(const float4*)&W[(size_t)(k0 + br + i * 8) * 512 + col0 + bc];
            *(float4*)&Bs[br + i * 8][bc] = b4;
        }
        __syncthreads();
#pragma unroll
        for (int kk = 0; kk < 16; kk++) {
            float a[8], b[8];
            *(float4*)&a[0] = *(const float4*)&As[kk][ty * 8];
            *(float4*)&a[4] = *(const float4*)&As[kk][ty * 8 + 4];
            *(float4*)&b[0] = *(const float4*)&Bs[kk][tx * 8];
            *(float4*)&b[4] = *(const float4*)&Bs[kk][tx * 8 + 4];
#pragma unroll
            for (int i = 0; i < 8; i++)
#pragma unroll
                for (int j = 0; j < 8; j++)
                    acc[i][j] += a[i] * b[j];
        }
        __syncthreads();
    }

    // Epilogue: bias + scatter to head layout [B,H,S,HD]
#pragma unroll
    for (int i = 0; i < 8; i++) {
        int r = row0 + ty * 8 + i;
        int b = r >> 11;          // / 2048
        int s = r & 2047;
#pragma unroll
        for (int j = 0; j < 8; j++) {
            int c = col0 + tx * 8 + j;
            int h = c >> 6, hd = c & 63;
            dst[(((size_t)(b * 8 + h)) * 2048 + s) * 64 + hd] = acc[i][j] + bias[c];
        }
    }
}

// ---------------------------------------------------------------------------
// Output projection GEMM: out = g_O(8192x512) @ Wo + bo, flat [B,S,D].
// ---------------------------------------------------------------------------
__global__ __launch_bounds__(256) void out_proj_kernel(
    const float* __restrict__ Wo, const float* __restrict__ bo,
    float* __restrict__ out)
{
    __shared__ float As[16][132];
    __shared__ float Bs[16][132];

    const int tid = threadIdx.x;
    const int tx = tid & 15, ty = tid >> 4;
    const int row0 = blockIdx.y * 128;
    const int col0 = blockIdx.x * 128;

    float acc[8][8];
#pragma unroll
    for (int i = 0; i < 8; i++)
#pragma unroll
        for (int j = 0; j < 8; j++) acc[i][j] = 0.f;

    const int ar = tid >> 2;
    const int ak = (tid & 3) * 4;
    const int br = tid >> 5;
    const int bc = (tid & 31) * 4;

    for (int k0 = 0; k0 < 512; k0 += 16) {
#pragma unroll
        for (int i = 0; i < 2; i++) {
            float4 a4 = *(const float4*)&g_O[(size_t)(row0 + ar + i * 64) * 512 + k0 + ak];
            As[ak + 0][ar + i * 64] = a4.x;
            As[ak + 1][ar + i * 64] = a4.y;
            As[ak + 2][ar + i * 64] = a4.z;
            As[ak + 3][ar + i * 64] = a4.w;
        }
#pragma unroll
        for (int i = 0; i < 2; i++) {
            float4 b4 = *(const float4*)&Wo[(size_t)(k0 + br + i * 8) * 512 + col0 + bc];
            *(float4*)&Bs[br + i * 8][bc] = b4;
        }
        __syncthreads();
#pragma unroll
        for (int kk = 0; kk < 16; kk++) {
            float a[8], b[8];
            *(float4*)&a[0] = *(const float4*)&As[kk][ty * 8];
            *(float4*)&a[4] = *(const float4*)&As[kk][ty * 8 + 4];
            *(float4*)&b[0] = *(const float4*)&Bs[kk][tx * 8];
            *(float4*)&b[4] = *(const float4*)&Bs[kk][tx * 8 + 4];
#pragma unroll
            for (int i = 0; i < 8; i++)
#pragma unroll
                for (int j = 0; j < 8; j++)
                    acc[i][j] += a[i] * b[j];
        }
        __syncthreads();
    }

#pragma unroll
    for (int i = 0; i < 8; i++) {
        int r = row0 + ty * 8 + i;
#pragma unroll
        for (int j = 0; j < 8; j++) {
            int c = col0 + tx * 8 + j;
            out[(size_t)r * 512 + c] = acc[i][j] + bo[c];
        }
    }
}

// ---------------------------------------------------------------------------
// Fused flash attention per (b,h): 64 q-rows per block, 64-key tiles,
// online softmax. Skips tiles entirely past valid_len (exact in fp32:
// exp(-1e6 - m) underflows to 0 whenever any valid key exists).
// Dynamic smem: Qs/Ks/Vs/Ps 64x64 each + 3*64 stats = 66304 B.
// ---------------------------------------------------------------------------
__global__ __launch_bounds__(256) void attn_kernel(const int* __restrict__ valid_lens)
{
    extern __shared__ float sm[];
    float* Qs = sm;              // 64*64
    float* Ks = sm + 4096;
    float* Vs = sm + 8192;
    float* Ps = sm + 12288;      // scores -> probs
    float* mS = sm + 16384;      // running max per row
    float* lS = mS + 64;         // running sum per row
    float* aS = lS + 64;         // rescale factor per row

    const int bh = blockIdx.y;            // 0..31
    const int b = bh >> 3, h = bh & 7;
    const int q0 = blockIdx.x * 64;
    const int tid = threadIdx.x;
    const int tx = tid & 15, ty = tid >> 4;

    const float* Qg = g_Q + (size_t)bh * (2048 * 64);
    const float* Kg = g_K + (size_t)bh * (2048 * 64);
    const float* Vg = g_V + (size_t)bh * (2048 * 64);

    const int vlen = valid_lens[b];
    int ntiles = (vlen > 0) ? ((vlen + 63) >> 6) : 32;
    if (ntiles > 32) ntiles = 32;

    // Load Q tile (64x64), coalesced float4
    {
        const int r = tid >> 4;
        const int cg = (tid & 15) * 4;
#pragma unroll
        for (int i = 0; i < 4; i++)
            *(float4*)&Qs[(r + i * 16) * 64 + cg] =
                *(const float4*)&Qg[(size_t)(q0 + r + i * 16) * 64 + cg];
    }
    if (tid < 64) { mS[tid] = -1e30f; lS[tid] = 0.f; }
    float o[4][4] = {};
    __syncthreads();

    for (int kt = 0; kt < ntiles; kt++) {
        const int ks0 = kt << 6;
        {
            const int r = tid >> 4;
            const int cg = (tid & 15) * 4;
#pragma unroll
            for (int i = 0; i < 4; i++) {
                *(float4*)&Ks[(r + i * 16) * 64 + cg] =
                    *(const float4*)&Kg[(size_t)(ks0 + r + i * 16) * 64 + cg];
                *(float4*)&Vs[(r + i * 16) * 64 + cg] =
                    *(const float4*)&Vg[(size_t)(ks0 + r + i * 16) * 64 + cg];
            }
        }
        __syncthreads();

        // S = Q @ K^T
        float acc[4][4] = {};
#pragma unroll
        for (int kk = 0; kk < 64; kk++) {
            float a[4], bb[4];
#pragma unroll
            for (int i = 0; i < 4; i++) a[i] = Qs[(ty * 4 + i) * 64 + kk];
#pragma unroll
            for (int j = 0; j < 4; j++) bb[j] = Ks[(tx * 4 + j) * 64 + kk];
#pragma unroll
            for (int i = 0; i < 4; i++)
#pragma unroll
                for (int j = 0; j < 4; j++)
                    acc[i][j] += a[i] * bb[j];
        }
        // scale + mask, write to Ps
#pragma unroll
        for (int i = 0; i < 4; i++)
#pragma unroll
            for (int j = 0; j < 4; j++) {
                int c = tx * 4 + j;
                float sv = acc[i][j] * 0.125f;        // 1/sqrt(64)
                if (ks0 + c >= vlen) sv = -1e6f;      // d2l mask semantics
                Ps[(ty * 4 + i) * 64 + c] = sv;
            }
        __syncthreads();

        // Online softmax update, one thread per row
        if (tid < 64) {
            float mold = mS[tid];
            float mx = mold;
            for (int c = 0; c < 64; c++) mx = fmaxf(mx, Ps[tid * 64 + c]);
            float alpha = __expf(mold - mx);
            float ssum = 0.f;
            for (int c = 0; c < 64; c++) {
                float p = __expf(Ps[tid * 64 + c] - mx);
                Ps[tid * 64 + c] = p;
                ssum += p;
            }
            mS[tid] = mx;
            lS[tid] = lS[tid] * alpha + ssum;
            aS[tid] = alpha;
        }
        __syncthreads();

        // O = O * alpha + P @ V
        float al[4];
#pragma unroll
        for (int i = 0; i < 4; i++) al[i] = aS[ty * 4 + i];
#pragma unroll
        for (int i = 0; i < 4; i++)
#pragma unroll
            for (int j = 0; j < 4; j++) o[i][j] *= al[i];

#pragma unroll
        for (int kk = 0; kk < 64; kk++) {
            float p[4], vv[4];
#pragma unroll
            for (int i = 0; i < 4; i++) p[i] = Ps[(ty * 4 + i) * 64 + kk];
#pragma unroll
            for (int j = 0; j < 4; j++) vv[j] = Vs[kk * 64 + tx * 4 + j];
#pragma unroll
            for (int i = 0; i < 4; i++)
#pragma unroll
                for (int j = 0; j < 4; j++)
                    o[i][j] += p[i] * vv[j];
        }
        __syncthreads();
    }

    // Final normalize + write to [B,S,D] layout
#pragma unroll
    for (int i = 0; i < 4; i++) {
        float inv = 1.f / lS[ty * 4 + i];
        int r = q0 + ty * 4 + i;
#pragma unroll
        for (int j = 0; j < 4; j++)
            g_O[((size_t)b * 2048 + r) * 512 + h * 64 + tx * 4 + j] = o[i][j] * inv;
    }
}

// ---------------------------------------------------------------------------
extern "C" void kernel_launch(void* const* d_in, const int* in_sizes, int n_in,
                              void* d_out, int out_size)
{
    const float* queries = (const float*)d_in[0];
    const float* keys    = (const float*)d_in[1];
    const float* values  = (const float*)d_in[2];
    const int*   vlens   = (const int*)d_in[3];
    const float* Wq = (const float*)d_in[4];
    const float* bq = (const float*)d_in[5];
    const float* Wk = (const float*)d_in[6];
    const float* bk = (const float*)d_in[7];
    const float* Wv = (const float*)d_in[8];
    const float* bv = (const float*)d_in[9];
    const float* Wo = (const float*)d_in[10];
    const float* bo = (const float*)d_in[11];
    float* out = (float*)d_out;

    // Q/K/V projections (z selects matrix)
    qkv_proj_kernel<<<dim3(4, 64, 3), 256>>>(queries, keys, values,
                                             Wq, bq, Wk, bk, Wv, bv);

    // Flash attention
    const int smem_bytes = (4 * 4096 + 3 * 64) * sizeof(float);   // 66304
    cudaFuncSetAttribute(attn_kernel,
                         cudaFuncAttributeMaxDynamicSharedMemorySize, smem_bytes);
    attn_kernel<<<dim3(32, 32), 256, smem_bytes>>>(vlens);

    // Output projection
    out_proj_kernel<<<dim3(4, 64), 256>>>(Wo, bo, out);
}

// round 2
// speedup vs baseline: 2.2118x; 2.2118x over previous
#include <cuda_runtime.h>

// Problem constants: B=4, S=2048, D=512, H=8, HD=64

__device__ float g_Q[4 * 8 * 2048 * 64];   // [B,H,S,HD]
__device__ float g_K[4 * 8 * 2048 * 64];
__device__ float g_V[4 * 8 * 2048 * 64];
__device__ float g_O[4 * 2048 * 512];      // [B,S,D] attention output

// ---------------------------------------------------------------------------
// Fused QKV projection GEMM: C = A(8192x512) @ W(512x512) + bias,
// stored in head layout [B,H,S,HD]. blockIdx.z selects Q/K/V.
// 128x128 tile, BK=16, 256 threads, 8x8 micro-tile. 2 CTAs/SM.
// ---------------------------------------------------------------------------
__global__ __launch_bounds__(256, 2) void qkv_proj_kernel(
    const float* __restrict__ Qin, const float* __restrict__ Kin,
    const float* __restrict__ Vin,
    const float* __restrict__ Wq, const float* __restrict__ bq,
    const float* __restrict__ Wk, const float* __restrict__ bk,
    const float* __restrict__ Wv, const float* __restrict__ bv)
{
    const int mat = blockIdx.z;
    const float* A    = (mat == 0) ? Qin : (mat == 1) ? Kin : Vin;
    const float* W    = (mat == 0) ? Wq  : (mat == 1) ? Wk  : Wv;
    const float* bias = (mat == 0) ? bq  : (mat == 1) ? bk  : bv;
    float* dst        = (mat == 0) ? g_Q : (mat == 1) ? g_K : g_V;

    __shared__ float As[16][132];   // [k][m], padded
    __shared__ float Bs[16][132];   // [k][n], padded

    const int tid = threadIdx.x;
    const int tx = tid & 15, ty = tid >> 4;
    const int row0 = blockIdx.y * 128;
    const int col0 = blockIdx.x * 128;

    float acc[8][8];
#pragma unroll
    for (int i = 0; i < 8; i++)
#pragma unroll
        for (int j = 0; j < 8; j++) acc[i][j] = 0.f;

    const int ar = tid >> 2;          // 0..63
    const int ak = (tid & 3) * 4;
    const int br = tid >> 5;          // 0..7
    const int bc = (tid & 31) * 4;

    for (int k0 = 0; k0 < 512; k0 += 16) {
#pragma unroll
        for (int i = 0; i < 2; i++) {
            float4 a4 = *(const float4*)&A[(size_t)(row0 + ar + i * 64) * 512 + k0 + ak];
            As[ak + 0][ar + i * 64] = a4.x;
            As[ak + 1][ar + i * 64] = a4.y;
            As[ak + 2][ar + i * 64] = a4.z;
            As[ak + 3][ar + i * 64] = a4.w;
        }
#pragma unroll
        for (int i = 0; i < 2; i++) {
            float4 b4 = *(const float4*)&W[(size_t)(k0 + br + i * 8) * 512 + col0 + bc];
            *(float4*)&Bs[br + i * 8][bc] = b4;
        }
        __syncthreads();
#pragma unroll
        for (int kk = 0; kk < 16; kk++) {
            float a[8], b[8];
            *(float4*)&a[0] = *(const float4*)&As[kk][ty * 8];
            *(float4*)&a[4] = *(const float4*)&As[kk][ty * 8 + 4];
            *(float4*)&b[0] = *(const float4*)&Bs[kk][tx * 8];
            *(float4*)&b[4] = *(const float4*)&Bs[kk][tx * 8 + 4];
#pragma unroll
            for (int i = 0; i < 8; i++)
#pragma unroll
                for (int j = 0; j < 8; j++)
                    acc[i][j] += a[i] * b[j];
        }
        __syncthreads();
    }

#pragma unroll
    for (int i = 0; i < 8; i++) {
        int r = row0 + ty * 8 + i;
        int b = r >> 11;
        int s = r & 2047;
#pragma unroll
        for (int j = 0; j < 8; j++) {
            int c = col0 + tx * 8 + j;
            int h = c >> 6, hd = c & 63;
            dst[(((size_t)(b * 8 + h)) * 2048 + s) * 64 + hd] = acc[i][j] + bias[c];
        }
    }
}

// ---------------------------------------------------------------------------
// Output projection GEMM: out = g_O(8192x512) @ Wo + bo, flat [B,S,D].
// ---------------------------------------------------------------------------
__global__ __launch_bounds__(256, 2) void out_proj_kernel(
    const float* __restrict__ Wo, const float* __restrict__ bo,
    float* __restrict__ out)
{
    __shared__ float As[16][132];
    __shared__ float Bs[16][132];

    const int tid = threadIdx.x;
    const int tx = tid & 15, ty = tid >> 4;
    const int row0 = blockIdx.y * 128;
    const int col0 = blockIdx.x * 128;

    float acc[8][8];
#pragma unroll
    for (int i = 0; i < 8; i++)
#pragma unroll
        for (int j = 0; j < 8; j++) acc[i][j] = 0.f;

    const int ar = tid >> 2;
    const int ak = (tid & 3) * 4;
    const int br = tid >> 5;
    const int bc = (tid & 31) * 4;

    for (int k0 = 0; k0 < 512; k0 += 16) {
#pragma unroll
        for (int i = 0; i < 2; i++) {
            float4 a4 = *(const float4*)&g_O[(size_t)(row0 + ar + i * 64) * 512 + k0 + ak];
            As[ak + 0][ar + i * 64] = a4.x;
            As[ak + 1][ar + i * 64] = a4.y;
            As[ak + 2][ar + i * 64] = a4.z;
            As[ak + 3][ar + i * 64] = a4.w;
        }
#pragma unroll
        for (int i = 0; i < 2; i++) {
            float4 b4 = *(const float4*)&Wo[(size_t)(k0 + br + i * 8) * 512 + col0 + bc];
            *(float4*)&Bs[br + i * 8][bc] = b4;
        }
        __syncthreads();
#pragma unroll
        for (int kk = 0; kk < 16; kk++) {
            float a[8], b[8];
            *(float4*)&a[0] = *(const float4*)&As[kk][ty * 8];
            *(float4*)&a[4] = *(const float4*)&As[kk][ty * 8 + 4];
            *(float4*)&b[0] = *(const float4*)&Bs[kk][tx * 8];
            *(float4*)&b[4] = *(const float4*)&Bs[kk][tx * 8 + 4];
#pragma unroll
            for (int i = 0; i < 8; i++)
#pragma unroll
                for (int j = 0; j < 8; j++)
                    acc[i][j] += a[i] * b[j];
        }
        __syncthreads();
    }

#pragma unroll
    for (int i = 0; i < 8; i++) {
        int r = row0 + ty * 8 + i;
#pragma unroll
        for (int j = 0; j < 8; j++) {
            int c = col0 + tx * 8 + j;
            out[(size_t)r * 512 + c] = acc[i][j] + bo[c];
        }
    }
}

// ---------------------------------------------------------------------------
// Flash attention, register softmax. 64 q-rows per block, 64-key tiles.
// All smem tiles are k-major with an XOR group swizzle:
//   element (kk, c) lives at kk*64 + (((c>>2) ^ (kk>>2)) & 15)*4 + (c&3)
// so float4 reads at uniform kk are conflict-free and 16B aligned.
// ---------------------------------------------------------------------------
__device__ __forceinline__ int swi(int kk, int c) {
    return (kk << 6) + ((((c >> 2) ^ (kk >> 2)) & 15) << 2) + (c & 3);
}
__device__ __forceinline__ int swi4(int kk, int t) {   // float4 group t = c>>2
    return (kk << 6) + (((t ^ (kk >> 2)) & 15) << 2);
}

__global__ __launch_bounds__(256) void attn_kernel(const int* __restrict__ valid_lens)
{
    extern __shared__ float sm[];
    float* Qt = sm;               // [hd][q]   64x64 swizzled
    float* Kt = sm + 4096;        // [hd][key] 64x64 swizzled
    float* Vs = sm + 8192;        // [key][hd] 64x64 swizzled
    float* Pt = sm + 12288;       // [key][q]  64x64 swizzled

    const int bh = blockIdx.y;            // 0..31
    const int b = bh >> 3, h = bh & 7;
    const int q0 = blockIdx.x * 64;
    const int tid = threadIdx.x;
    const int tx = tid & 15, ty = tid >> 4;

    const float* Qg = g_Q + (size_t)bh * (2048 * 64);
    const float* Kg = g_K + (size_t)bh * (2048 * 64);
    const float* Vg = g_V + (size_t)bh * (2048 * 64);

    const int vlen = valid_lens[b];
    int ntiles = (vlen > 0) ? ((vlen + 63) >> 6) : 32;
    if (ntiles > 32) ntiles = 32;

    const int lr = tid >> 4;             // 0..15 loader row
    const int lc = (tid & 15) * 4;       // loader col group*4

    // Load Q tile transposed (k-major) once
#pragma unroll
    for (int i2 = 0; i2 < 4; i2++) {
        int row = lr + i2 * 16;
        float4 q4 = *(const float4*)&Qg[(size_t)(q0 + row) * 64 + lc];
        Qt[swi(lc + 0, row)] = q4.x;
        Qt[swi(lc + 1, row)] = q4.y;
        Qt[swi(lc + 2, row)] = q4.z;
        Qt[swi(lc + 3, row)] = q4.w;
    }

    float o[4][4] = {};
    float m[4], l[4];
#pragma unroll
    for (int i = 0; i < 4; i++) { m[i] = -1e30f; l[i] = 0.f; }

    for (int kt = 0; kt < ntiles; kt++) {
        const int ks0 = kt << 6;
        __syncthreads();   // previous PV done reading Kt/Vs/Pt

        // Load K transposed (k-major) + V natural, both swizzled
#pragma unroll
        for (int i2 = 0; i2 < 4; i2++) {
            int row = lr + i2 * 16;
            float4 k4 = *(const float4*)&Kg[(size_t)(ks0 + row) * 64 + lc];
            Kt[swi(lc + 0, row)] = k4.x;
            Kt[swi(lc + 1, row)] = k4.y;
            Kt[swi(lc + 2, row)] = k4.z;
            Kt[swi(lc + 3, row)] = k4.w;
            float4 v4 = *(const float4*)&Vg[(size_t)(ks0 + row) * 64 + lc];
            *(float4*)&Vs[swi4(row, lc >> 2)] = v4;
        }
        __syncthreads();

        // S = Q @ K^T (rows 4ty.., cols 4tx..)
        float acc[4][4] = {};
#pragma unroll
        for (int kk = 0; kk < 64; kk++) {
            float4 a4 = *(const float4*)&Qt[swi4(kk, ty)];
            float4 b4 = *(const float4*)&Kt[swi4(kk, tx)];
            float a[4] = {a4.x, a4.y, a4.z, a4.w};
            float bb[4] = {b4.x, b4.y, b4.z, b4.w};
#pragma unroll
            for (int i = 0; i < 4; i++)
#pragma unroll
                for (int j = 0; j < 4; j++)
                    acc[i][j] += a[i] * bb[j];
        }

        // Register online softmax; rows reduce across the 16 lanes sharing ty
#pragma unroll
        for (int i = 0; i < 4; i++) {
#pragma unroll
            for (int j = 0; j < 4; j++) {
                float sv = acc[i][j] * 0.125f;               // 1/sqrt(64)
                if (ks0 + tx * 4 + j >= vlen) sv = -1e6f;    // d2l mask
                acc[i][j] = sv;
            }
            float tm = fmaxf(fmaxf(acc[i][0], acc[i][1]), fmaxf(acc[i][2], acc[i][3]));
#pragma unroll
            for (int off = 1; off < 16; off <<= 1)
                tm = fmaxf(tm, __shfl_xor_sync(0xffffffffu, tm, off));
            float mnew = fmaxf(m[i], tm);
            float alpha = __expf(m[i] - mnew);
            float rs = 0.f;
#pragma unroll
            for (int j = 0; j < 4; j++) {
                float p = __expf(acc[i][j] - mnew);
                acc[i][j] = p;
                rs += p;
            }
#pragma unroll
            for (int off = 1; off < 16; off <<= 1)
                rs += __shfl_xor_sync(0xffffffffu, rs, off);
            m[i] = mnew;
            l[i] = l[i] * alpha + rs;
#pragma unroll
            for (int j = 0; j < 4; j++) o[i][j] *= alpha;
            // store P transposed: Pt[c][r]
#pragma unroll
            for (int j = 0; j < 4; j++)
                Pt[((tx * 4 + j) << 6) + (((ty ^ tx) & 15) << 2) + i] = acc[i][j];
        }
        __syncthreads();

        // O += P @ V
#pragma unroll
        for (int kk = 0; kk < 64; kk++) {
            float4 p4 = *(const float4*)&Pt[swi4(kk, ty)];
            float4 v4 = *(const float4*)&Vs[swi4(kk, tx)];
            float p[4] = {p4.x, p4.y, p4.z, p4.w};
            float vv[4] = {v4.x, v4.y, v4.z, v4.w};
#pragma unroll
            for (int i = 0; i < 4; i++)
#pragma unroll
                for (int j = 0; j < 4; j++)
                    o[i][j] += p[i] * vv[j];
        }
    }

    // Final normalize + write to [B,S,D]
#pragma unroll
    for (int i = 0; i < 4; i++) {
        float inv = 1.f / l[i];
        int r = q0 + ty * 4 + i;
        float4 w4 = make_float4(o[i][0] * inv, o[i][1] * inv, o[i][2] * inv, o[i][3] * inv);
        *(float4*)&g_O[((size_t)b * 2048 + r) * 512 + h * 64 + tx * 4] = w4;
    }
}

// ---------------------------------------------------------------------------
extern "C" void kernel_launch(void* const* d_in, const int* in_sizes, int n_in,
                              void* d_out, int out_size)
{
    const float* queries = (const float*)d_in[0];
    const float* keys    = (const float*)d_in[1];
    const float* values  = (const float*)d_in[2];
    const int*   vlens   = (const int*)d_in[3];
    const float* Wq = (const float*)d_in[4];
    const float* bq = (const float*)d_in[5];
    const float* Wk = (const float*)d_in[6];
    const float* bk = (const float*)d_in[7];
    const float* Wv = (const float*)d_in[8];
    const float* bv = (const float*)d_in[9];
    const float* Wo = (const float*)d_in[10];
    const float* bo = (const float*)d_in[11];
    float* out = (float*)d_out;

    qkv_proj_kernel<<<dim3(4, 64, 3), 256>>>(queries, keys, values,
                                             Wq, bq, Wk, bk, Wv, bv);

    const int smem_bytes = 4 * 4096 * sizeof(float);   // 64 KB
    cudaFuncSetAttribute(attn_kernel,
                         cudaFuncAttributeMaxDynamicSharedMemorySize, smem_bytes);
    attn_kernel<<<dim3(32, 32), 256, smem_bytes>>>(vlens);

    out_proj_kernel<<<dim3(4, 64), 256>>>(Wo, bo, out);
}